// round 4
// baseline (speedup 1.0000x reference)
#include <cuda_runtime.h>
#include <cstdint>
#include <cstddef>

#define S_DIM 8
#define U_DIM 8
#define SU    64
#define NK    12
#define NEG   17
#define ZD    64
#define CD    256
#define T_DIM 1140
#define LEN   1128
#define MROWS (SU * LEN)          // 72192 flattened (su,l) rows
#define SCALE 0.125f

// Double-buffered scratch: Wc[buf][su*LEN + l][z]  (2 x ~18.5 MB)
__device__ float  g_Wc[2][(size_t)MROWS * ZD];
__device__ double g_loss[NK];
__device__ int    g_acc[NK];

// ---------------------------------------------------------------------------
// Packed fp32x2 helpers (exact fp32 semantics, 2x fma issue density)
// ---------------------------------------------------------------------------
__device__ __forceinline__ void ffma2(unsigned long long& acc,
                                      unsigned long long a,
                                      unsigned long long b)
{
    asm("fma.rn.f32x2 %0, %1, %2, %3;" : "=l"(acc) : "l"(a), "l"(b), "l"(acc));
}
__device__ __forceinline__ unsigned long long splat2(float v)
{
    unsigned long long r;
    asm("mov.b64 %0, {%1, %1};" : "=l"(r) : "f"(v));
    return r;
}
__device__ __forceinline__ void unpack2(unsigned long long v, float& lo, float& hi)
{
    asm("mov.b64 {%0, %1}, %2;" : "=f"(lo), "=f"(hi) : "l"(v));
}

// ---------------------------------------------------------------------------
// Fused launch: grid = [0,282) gemm blocks for step kk,
//               [282, 282+768) score blocks for step kk-1.
// gemm(k) -> score(k) ordering enforced by launch boundary; gemm(kk) and
// score(kk-1) use different Wc buffers so intra-launch order is free.
// ---------------------------------------------------------------------------
#define GEMM_BLOCKS  282           // 282 * 256 = 72192 = MROWS exactly
#define SCORE_BLOCKS 768           // 12 l-chunks * 64 su
#define BK 16
#define BM 256

struct SmemGemm {
    float cs[BK][BM + 4];          // [d][m]
    float ws[BK][ZD + 4];          // [d][z]
};
struct SmemScore {
    int   sbi[NEG];
    float blk_loss;
    int   blk_acc;
};
union SmemU { SmemGemm g; SmemScore s; };

// ---------------- GEMM body: Wc[r][z] = sum_d c_row(r)[d]*W[k][z][d] + b ----
__device__ __forceinline__ void gemm_body(
    SmemGemm& sm, const float* __restrict__ c, const float* __restrict__ W,
    const float* __restrict__ bias, const int kk, float* __restrict__ wcout)
{
    const int tid = threadIdx.x;
    const int tm = tid >> 4;       // 0..15 -> 16 rows each
    const int tn = tid & 15;       // 0..15 -> 4 z each
    const int r0 = blockIdx.x * BM;

    unsigned long long acc[8][4];  // pair p = rows (2p,2p+1), col j
    #pragma unroll
    for (int p = 0; p < 8; p++)
        #pragma unroll
        for (int j = 0; j < 4; j++) acc[p][j] = 0ull;

    const float* wb = W + (size_t)kk * ZD * CD;

    for (int d0 = 0; d0 < CD; d0 += BK) {
        // c tile: 256 rows x 16 d  (4 float4 per thread), rows flat over (su,l)
        #pragma unroll
        for (int i = 0; i < 4; i++) {
            int idx = tid + i * 256;
            int m   = idx >> 2;
            int dq  = (idx & 3) * 4;
            int r   = r0 + m;                 // < MROWS by construction
            int su  = r / LEN;
            int l   = r - su * LEN;
            float4 v = *(const float4*)(c + ((size_t)su * T_DIM + l) * CD + d0 + dq);
            sm.cs[dq + 0][m] = v.x; sm.cs[dq + 1][m] = v.y;
            sm.cs[dq + 2][m] = v.z; sm.cs[dq + 3][m] = v.w;
        }
        // W tile: 64 z x 16 d (1 float4 per thread)
        {
            int zr = tid >> 2;
            int dq = (tid & 3) * 4;
            float4 v = *(const float4*)(wb + (size_t)zr * CD + d0 + dq);
            sm.ws[dq + 0][zr] = v.x; sm.ws[dq + 1][zr] = v.y;
            sm.ws[dq + 2][zr] = v.z; sm.ws[dq + 3][zr] = v.w;
        }
        __syncthreads();

        #pragma unroll
        for (int d = 0; d < BK; d++) {
            ulonglong2 aA = *(const ulonglong2*)&sm.cs[d][tm * 16 + 0];
            ulonglong2 aB = *(const ulonglong2*)&sm.cs[d][tm * 16 + 4];
            ulonglong2 aC = *(const ulonglong2*)&sm.cs[d][tm * 16 + 8];
            ulonglong2 aD = *(const ulonglong2*)&sm.cs[d][tm * 16 + 12];
            unsigned long long ap[8] = {aA.x, aA.y, aB.x, aB.y,
                                        aC.x, aC.y, aD.x, aD.y};
            float4 b = *(const float4*)&sm.ws[d][tn * 4];
            unsigned long long bs[4] = {splat2(b.x), splat2(b.y),
                                        splat2(b.z), splat2(b.w)};
            #pragma unroll
            for (int p = 0; p < 8; p++)
                #pragma unroll
                for (int j = 0; j < 4; j++)
                    ffma2(acc[p][j], ap[p], bs[j]);
        }
        __syncthreads();
    }

    float4 bv = *(const float4*)(bias + kk * ZD + tn * 4);
    const float bvf[4] = {bv.x, bv.y, bv.z, bv.w};
    #pragma unroll
    for (int p = 0; p < 8; p++) {
        float r0v[4], r1v[4];
        #pragma unroll
        for (int j = 0; j < 4; j++) {
            unpack2(acc[p][j], r0v[j], r1v[j]);
            r0v[j] += bvf[j]; r1v[j] += bvf[j];
        }
        size_t rA = (size_t)(r0 + tm * 16 + 2 * p);
        *(float4*)(wcout + rA * ZD + tn * 4) =
            make_float4(r0v[0], r0v[1], r0v[2], r0v[3]);
        *(float4*)(wcout + (rA + 1) * ZD + tn * 4) =
            make_float4(r1v[0], r1v[1], r1v[2], r1v[3]);
    }
}

// ---------------- Score body (step kk, reading wc buffer) -------------------
// 8-lane groups own one l each; lane owns 8 of 64 dims. Warp = 4 l's.
__device__ __forceinline__ void score_body(
    SmemScore& sm, const float* __restrict__ z, const int* __restrict__ bidx,
    const int* __restrict__ sidx, const int kk, const float* __restrict__ wc,
    const int sb)
{
    const int su = sb & 63;
    const int bx = sb >> 6;              // 0..11
    const int s = su >> 3, u = su & 7;
    const int tid = threadIdx.x;

    if (tid < NEG) sm.sbi[tid] = bidx[(kk * U_DIM + u) * NEG + tid];
    if (tid == 0) { sm.blk_loss = 0.f; sm.blk_acc = 0; }
    __syncthreads();

    const int warp = tid >> 5, lane = tid & 31;
    const int grp = lane >> 3, lg = lane & 7;
    const int gg = (bx * 8 + warp) * 4 + grp;        // 0..383
    const int d0 = lg * 8;

    const float* wcb = wc + (size_t)su * LEN * ZD;
    const int*   sib = sidx + ((((size_t)kk * S_DIM + s) * U_DIM + u) * NEG) * LEN;
    const float* zsp = z + (size_t)(s * U_DIM) * T_DIM * ZD;

    float loss_local = 0.f;
    int   acc_local  = 0;

    #pragma unroll
    for (int it = 0; it < 3; it++) {
        const int l = gg + 384 * it;
        const bool valid = (l < LEN);
        const int lx = valid ? l : 0;

        const float4 wa = *(const float4*)(wcb + (size_t)lx * ZD + d0);
        const float4 wb = *(const float4*)(wcb + (size_t)lx * ZD + d0 + 4);

        float f[NEG + 1];
        {
            const float* zr = z + ((size_t)su * T_DIM + (lx + kk + 1)) * ZD + d0;
            const float4 p0 = *(const float4*)zr;
            const float4 p1 = *(const float4*)(zr + 4);
            f[0] = p0.x * wa.x + p0.y * wa.y + p0.z * wa.z + p0.w * wa.w
                 + p1.x * wb.x + p1.y * wb.y + p1.z * wb.z + p1.w * wb.w;
        }
        #pragma unroll
        for (int n = 0; n < NEG; n++) {
            const int si = sib[(size_t)n * LEN + lx];
            const int bi = sm.sbi[n];
            const float* zr = zsp + ((size_t)bi * T_DIM + (si + kk + 1)) * ZD + d0;
            const float4 p0 = *(const float4*)zr;
            const float4 p1 = *(const float4*)(zr + 4);
            f[1 + n] = p0.x * wa.x + p0.y * wa.y + p0.z * wa.z + p0.w * wa.w
                     + p1.x * wb.x + p1.y * wb.y + p1.z * wb.z + p1.w * wb.w;
        }

        #pragma unroll
        for (int off = 4; off; off >>= 1)
            #pragma unroll
            for (int i = 0; i < NEG + 1; i++)
                f[i] += __shfl_xor_sync(0xffffffffu, f[i], off);

        f[0] *= SCALE;
        float m = f[0]; int am = 0;
        #pragma unroll
        for (int i = 1; i < NEG + 1; i++) {
            f[i] *= SCALE;
            if (f[i] > m) { m = f[i]; am = i; }
        }
        float ssum = 0.f;
        #pragma unroll
        for (int i = 0; i < NEG + 1; i++) ssum += __expf(f[i] - m);

        if (valid) {
            loss_local += (m + __logf(ssum)) - f[0];
            acc_local  += (am == 0) ? 1 : 0;
        }
    }

    float lval = (lg == 0) ? loss_local : 0.f;
    int   aval = (lg == 0) ? acc_local  : 0;
    lval += __shfl_xor_sync(0xffffffffu, lval, 8);
    lval += __shfl_xor_sync(0xffffffffu, lval, 16);
    aval += __shfl_xor_sync(0xffffffffu, aval, 8);
    aval += __shfl_xor_sync(0xffffffffu, aval, 16);
    if (lane == 0) {
        atomicAdd(&sm.blk_loss, lval);
        atomicAdd(&sm.blk_acc, aval);
    }
    __syncthreads();
    if (tid == 0) {
        atomicAdd(&g_loss[kk], (double)sm.blk_loss);
        atomicAdd(&g_acc[kk], sm.blk_acc);
    }
}

// ---------------- Fused kernel ---------------------------------------------
__global__ __launch_bounds__(256) void fused_step(
    const float* __restrict__ z, const float* __restrict__ c,
    const float* __restrict__ W, const float* __restrict__ bias,
    const int* __restrict__ bidx, const int* __restrict__ sidx,
    const int kk)
{
    __shared__ __align__(16) SmemU sm;
    const int bx = blockIdx.x;
    if (bx < GEMM_BLOCKS) {
        if (kk < NK)
            gemm_body(sm.g, c, W, bias, kk, g_Wc[kk & 1]);
    } else {
        if (kk > 0)
            score_body(sm.s, z, bidx, sidx, kk - 1, g_Wc[(kk - 1) & 1],
                       bx - GEMM_BLOCKS);
    }
}

// ---------------- zero / finalize ------------------------------------------
__global__ void zero_kernel()
{
    int t = threadIdx.x;
    if (t < NK) { g_loss[t] = 0.0; g_acc[t] = 0; }
}

__global__ void final_kernel(float* __restrict__ out)
{
    int t = threadIdx.x;
    if (t < NK)
        out[1 + t] = (float)((double)g_acc[t] / (double)(SU * LEN));
    if (t == 0) {
        double tot = 0.0;
        for (int i = 0; i < NK; i++) tot += g_loss[i];   // fixed order
        out[0] = (float)(tot / ((double)NK * SU * LEN));
    }
}

// ---------------------------------------------------------------------------
extern "C" void kernel_launch(void* const* d_in, const int* in_sizes, int n_in,
                              void* d_out, int out_size)
{
    const float* z    = (const float*)d_in[0];
    const float* c    = (const float*)d_in[1];
    const float* W    = (const float*)d_in[2];
    const float* b    = (const float*)d_in[3];
    const int*   bidx = (const int*)d_in[4];
    const int*   sidx = (const int*)d_in[5];
    float* out = (float*)d_out;

    zero_kernel<<<1, 32>>>();
    for (int kk = 0; kk <= NK; kk++)   // 13 pipelined launches
        fused_step<<<GEMM_BLOCKS + SCORE_BLOCKS, 256>>>(z, c, W, b, bidx, sidx, kk);
    final_kernel<<<1, 32>>>(out);
}

// round 6
// speedup vs baseline: 1.0152x; 1.0152x over previous
#include <cuda_runtime.h>
#include <cstdint>
#include <cstddef>

#define S_DIM 8
#define U_DIM 8
#define SU    64
#define NK    12
#define NEG   17
#define ZD    64
#define CD    256
#define T_DIM 1140
#define LEN   1128
#define MROWS (SU * LEN)          // 72192 flattened (su,l) rows
#define SCALE 0.125f

// Scratch: Wc[su*LEN + l][z] for one k (~18.5 MB, L2-resident for score).
__device__ float  g_Wc[(size_t)MROWS * ZD];
__device__ double g_loss[NK];
__device__ int    g_acc[NK];

// ---------------------------------------------------------------------------
// Packed fp32x2 helpers (exact fp32 semantics, 2x fma issue density)
// ---------------------------------------------------------------------------
__device__ __forceinline__ void ffma2(unsigned long long& acc,
                                      unsigned long long a,
                                      unsigned long long b)
{
    asm("fma.rn.f32x2 %0, %1, %2, %3;" : "=l"(acc) : "l"(a), "l"(b), "l"(acc));
}
__device__ __forceinline__ unsigned long long splat2(float v)
{
    unsigned long long r;
    asm("mov.b64 %0, {%1, %1};" : "=l"(r) : "f"(v));
    return r;
}
__device__ __forceinline__ void unpack2(unsigned long long v, float& lo, float& hi)
{
    asm("mov.b64 {%0, %1}, %2;" : "=f"(lo), "=f"(hi) : "l"(v));
}

// ---------------------------------------------------------------------------
// Kernel 1: Wc[r][z] = sum_d c_row(r)[d] * W[k][z][d] + b[k][z]
// BM=256 rows x 64 z, BK=16. Thread map: tm = tid>>3 (8 rows), tn = tid&7
// (8 z). Per d: 4 LDS.128 (a broadcast-pairs) + 2 LDS.128 (b) + 8 splat MOV
// + 32 FFMA2 -> 16 MACs per smem wavefront (2x R3), fma-pipe bound.
// Grid = 282 blocks (exact), 2 CTAs/SM -> single full wave.
// ---------------------------------------------------------------------------
#define BK 16
#define BM 256

__global__ __launch_bounds__(256, 2) void gemm_wc(
    const float* __restrict__ c, const float* __restrict__ W,
    const float* __restrict__ bias, const int kk)
{
    __shared__ __align__(16) float cs[BK][BM + 4];   // [d][m]
    __shared__ __align__(16) float ws[BK][ZD + 4];   // [d][z]

    const int tid = threadIdx.x;
    const int tm = tid >> 3;      // 0..31 -> rows tm*8 .. tm*8+7
    const int tn = tid & 7;       // 0..7  -> cols tn*8 .. tn*8+7
    const int r0 = blockIdx.x * BM;

    // acc[p][j]: packed row-pair (2p,2p+1) x col j (8 cols)
    unsigned long long acc[4][8];
    #pragma unroll
    for (int p = 0; p < 4; p++)
        #pragma unroll
        for (int j = 0; j < 8; j++) acc[p][j] = 0ull;

    const float* wb = W + (size_t)kk * ZD * CD;

    for (int d0 = 0; d0 < CD; d0 += BK) {
        // c tile: 256 rows x 16 d (4 float4/thread), rows flat over (su,l)
        #pragma unroll
        for (int i = 0; i < 4; i++) {
            int idx = tid + i * 256;
            int m   = idx >> 2;
            int dq  = (idx & 3) * 4;
            int r   = r0 + m;                 // < MROWS by construction
            int su  = r / LEN;
            int l   = r - su * LEN;
            float4 v = *(const float4*)(c + ((size_t)su * T_DIM + l) * CD + d0 + dq);
            cs[dq + 0][m] = v.x; cs[dq + 1][m] = v.y;
            cs[dq + 2][m] = v.z; cs[dq + 3][m] = v.w;
        }
        // W tile: 64 z x 16 d (1 float4/thread)
        {
            int zr = tid >> 2;
            int dq = (tid & 3) * 4;
            float4 v = *(const float4*)(wb + (size_t)zr * CD + d0 + dq);
            ws[dq + 0][zr] = v.x; ws[dq + 1][zr] = v.y;
            ws[dq + 2][zr] = v.z; ws[dq + 3][zr] = v.w;
        }
        __syncthreads();

        #pragma unroll
        for (int d = 0; d < BK; d++) {
            ulonglong2 a01 = *(const ulonglong2*)&cs[d][tm * 8];
            ulonglong2 a23 = *(const ulonglong2*)&cs[d][tm * 8 + 4];
            unsigned long long ap[4] = {a01.x, a01.y, a23.x, a23.y};
            float4 b0 = *(const float4*)&ws[d][tn * 8];
            float4 b1 = *(const float4*)&ws[d][tn * 8 + 4];
            unsigned long long bs[8] = {
                splat2(b0.x), splat2(b0.y), splat2(b0.z), splat2(b0.w),
                splat2(b1.x), splat2(b1.y), splat2(b1.z), splat2(b1.w)};
            #pragma unroll
            for (int p = 0; p < 4; p++)
                #pragma unroll
                for (int j = 0; j < 8; j++)
                    ffma2(acc[p][j], ap[p], bs[j]);
        }
        __syncthreads();
    }

    float4 bva = *(const float4*)(bias + kk * ZD + tn * 8);
    float4 bvb = *(const float4*)(bias + kk * ZD + tn * 8 + 4);
    const float bvf[8] = {bva.x, bva.y, bva.z, bva.w,
                          bvb.x, bvb.y, bvb.z, bvb.w};
    #pragma unroll
    for (int p = 0; p < 4; p++) {
        float r0v[8], r1v[8];
        #pragma unroll
        for (int j = 0; j < 8; j++) {
            unpack2(acc[p][j], r0v[j], r1v[j]);
            r0v[j] += bvf[j]; r1v[j] += bvf[j];
        }
        size_t rA = (size_t)(r0 + tm * 8 + 2 * p);
        float* o0 = g_Wc + rA * ZD + tn * 8;
        float* o1 = g_Wc + (rA + 1) * ZD + tn * 8;
        *(float4*)(o0)     = make_float4(r0v[0], r0v[1], r0v[2], r0v[3]);
        *(float4*)(o0 + 4) = make_float4(r0v[4], r0v[5], r0v[6], r0v[7]);
        *(float4*)(o1)     = make_float4(r1v[0], r1v[1], r1v[2], r1v[3]);
        *(float4*)(o1 + 4) = make_float4(r1v[4], r1v[5], r1v[6], r1v[7]);
    }
}

// ---------------------------------------------------------------------------
// Kernel 2: scoring for step k (R3 version — measured ~38us/launch).
// 8-lane groups own one l; lane owns 8 of 64 dims. Warp = 4 l's.
// ---------------------------------------------------------------------------
__global__ __launch_bounds__(256) void score_kernel(
    const float* __restrict__ z, const int* __restrict__ bidx,
    const int* __restrict__ sidx, const int kk)
{
    const int su = blockIdx.y;
    const int s = su >> 3, u = su & 7;
    const int tid = threadIdx.x;

    __shared__ int sbi[NEG];
    __shared__ float blk_loss;
    __shared__ int   blk_acc;
    if (tid < NEG) sbi[tid] = bidx[(kk * U_DIM + u) * NEG + tid];
    if (tid == 0) { blk_loss = 0.f; blk_acc = 0; }
    __syncthreads();

    const int warp = tid >> 5, lane = tid & 31;
    const int grp = lane >> 3, lg = lane & 7;
    const int gg = (blockIdx.x * 8 + warp) * 4 + grp;   // 0..383
    const int d0 = lg * 8;

    const float* wcb = g_Wc + (size_t)su * LEN * ZD;
    const int*   sib = sidx + ((((size_t)kk * S_DIM + s) * U_DIM + u) * NEG) * LEN;
    const float* zsp = z + (size_t)(s * U_DIM) * T_DIM * ZD;

    float loss_local = 0.f;
    int   acc_local  = 0;

    #pragma unroll
    for (int it = 0; it < 3; it++) {
        const int l = gg + 384 * it;
        const bool valid = (l < LEN);
        const int lx = valid ? l : 0;

        const float4 wa = *(const float4*)(wcb + (size_t)lx * ZD + d0);
        const float4 wb = *(const float4*)(wcb + (size_t)lx * ZD + d0 + 4);

        float f[NEG + 1];
        {
            const float* zr = z + ((size_t)su * T_DIM + (lx + kk + 1)) * ZD + d0;
            const float4 p0 = *(const float4*)zr;
            const float4 p1 = *(const float4*)(zr + 4);
            f[0] = p0.x * wa.x + p0.y * wa.y + p0.z * wa.z + p0.w * wa.w
                 + p1.x * wb.x + p1.y * wb.y + p1.z * wb.z + p1.w * wb.w;
        }
        #pragma unroll
        for (int n = 0; n < NEG; n++) {
            const int si = sib[(size_t)n * LEN + lx];
            const int bi = sbi[n];
            const float* zr = zsp + ((size_t)bi * T_DIM + (si + kk + 1)) * ZD + d0;
            const float4 p0 = *(const float4*)zr;
            const float4 p1 = *(const float4*)(zr + 4);
            f[1 + n] = p0.x * wa.x + p0.y * wa.y + p0.z * wa.z + p0.w * wa.w
                     + p1.x * wb.x + p1.y * wb.y + p1.z * wb.z + p1.w * wb.w;
        }

        #pragma unroll
        for (int off = 4; off; off >>= 1)
            #pragma unroll
            for (int i = 0; i < NEG + 1; i++)
                f[i] += __shfl_xor_sync(0xffffffffu, f[i], off);

        f[0] *= SCALE;
        float m = f[0]; int am = 0;
        #pragma unroll
        for (int i = 1; i < NEG + 1; i++) {
            f[i] *= SCALE;
            if (f[i] > m) { m = f[i]; am = i; }
        }
        float ssum = 0.f;
        #pragma unroll
        for (int i = 0; i < NEG + 1; i++) ssum += __expf(f[i] - m);

        if (valid) {
            loss_local += (m + __logf(ssum)) - f[0];
            acc_local  += (am == 0) ? 1 : 0;
        }
    }

    float lval = (lg == 0) ? loss_local : 0.f;
    int   aval = (lg == 0) ? acc_local  : 0;
    lval += __shfl_xor_sync(0xffffffffu, lval, 8);
    lval += __shfl_xor_sync(0xffffffffu, lval, 16);
    aval += __shfl_xor_sync(0xffffffffu, aval, 8);
    aval += __shfl_xor_sync(0xffffffffu, aval, 16);
    if (lane == 0) {
        atomicAdd(&blk_loss, lval);
        atomicAdd(&blk_acc, aval);
    }
    __syncthreads();
    if (tid == 0) {
        atomicAdd(&g_loss[kk], (double)blk_loss);
        atomicAdd(&g_acc[kk], blk_acc);
    }
}

// ---------------------------------------------------------------------------
// zero / finalize.  d_out layout: [loss, acc_0 .. acc_11]
// ---------------------------------------------------------------------------
__global__ void zero_kernel()
{
    int t = threadIdx.x;
    if (t < NK) { g_loss[t] = 0.0; g_acc[t] = 0; }
}

__global__ void final_kernel(float* __restrict__ out)
{
    int t = threadIdx.x;
    if (t < NK)
        out[1 + t] = (float)((double)g_acc[t] / (double)(SU * LEN));
    if (t == 0) {
        double tot = 0.0;
        for (int i = 0; i < NK; i++) tot += g_loss[i];   // fixed order
        out[0] = (float)(tot / ((double)NK * SU * LEN));
    }
}

// ---------------------------------------------------------------------------
extern "C" void kernel_launch(void* const* d_in, const int* in_sizes, int n_in,
                              void* d_out, int out_size)
{
    const float* z    = (const float*)d_in[0];
    const float* c    = (const float*)d_in[1];
    const float* W    = (const float*)d_in[2];
    const float* b    = (const float*)d_in[3];
    const int*   bidx = (const int*)d_in[4];
    const int*   sidx = (const int*)d_in[5];
    float* out = (float*)d_out;

    zero_kernel<<<1, 32>>>();
    for (int kk = 0; kk < NK; kk++) {
        gemm_wc<<<282, 256>>>(c, W, b, kk);
        score_kernel<<<dim3(12, SU), 256>>>(z, bidx, sidx, kk);
    }
    final_kernel<<<1, 32>>>(out);
}

// round 8
// speedup vs baseline: 1.2779x; 1.2588x over previous
#include <cuda_runtime.h>
#include <cuda_bf16.h>
#include <cstdint>
#include <cstddef>

#define S_DIM 8
#define U_DIM 8
#define SU    64
#define NK    12
#define NEG   17
#define ZD    64
#define CD    256
#define T_DIM 1140
#define LEN   1128
#define MROWS (SU * LEN)          // 72192 flattened (su,l) rows = 564 * 128
#define SCALE 0.125f

// Scratch: Wc[su*LEN + l][z] for one k (~18.5 MB, L2-resident for score).
__device__ float  g_Wc[(size_t)MROWS * ZD];
__device__ double g_loss[NK];
__device__ int    g_acc[NK];

// ---------------------------------------------------------------------------
// bf16 helpers
// ---------------------------------------------------------------------------
__device__ __forceinline__ uint32_t bpack(__nv_bfloat16 x, __nv_bfloat16 y)
{
    __nv_bfloat162 t = __halves2bfloat162(x, y);
    return *reinterpret_cast<uint32_t*>(&t);
}

// mma.sync m16n8k16 bf16: d += a * b   (f32 accumulate)
__device__ __forceinline__ void mma16816(float* d, const uint32_t* a,
                                         const uint32_t* b)
{
    asm volatile(
        "mma.sync.aligned.m16n8k16.row.col.f32.bf16.bf16.f32 "
        "{%0,%1,%2,%3}, {%4,%5,%6,%7}, {%8,%9}, {%0,%1,%2,%3};"
        : "+f"(d[0]), "+f"(d[1]), "+f"(d[2]), "+f"(d[3])
        : "r"(a[0]), "r"(a[1]), "r"(a[2]), "r"(a[3]), "r"(b[0]), "r"(b[1]));
}

// ---------------------------------------------------------------------------
// Kernel 1: Wc[r][z] = sum_d c_row(r)[d] * W[k][z][d] + b[k][z]
// via 2-term bf16 split: c ~= chi+clo, W ~= whi+wlo, all 4 cross products,
// f32 accumulation. |err| ~ 2^-18 relative.
// CTA = 128 rows x 64 z x K=256 (8 chunks of K=32). 8 warps, warp tile 32x32.
// Fragments loaded with plain LDS.32 per the documented m16n8k16 layouts.
// Smem stride 40 bf16 (80B rows): bank = (20g + tg) mod 32 -> conflict-free.
// ---------------------------------------------------------------------------
#define KC 32
#define SA 40   // A smem row stride in bf16
#define SB 40   // B smem row stride in bf16

__global__ __launch_bounds__(256) void gemm_hmma(
    const float* __restrict__ c, const float* __restrict__ W,
    const float* __restrict__ bias, const int kk)
{
    __shared__ __align__(16) __nv_bfloat16 Ahi[128 * SA];
    __shared__ __align__(16) __nv_bfloat16 Alo[128 * SA];
    __shared__ __align__(16) __nv_bfloat16 Bhi[ZD * SB];
    __shared__ __align__(16) __nv_bfloat16 Blo[ZD * SB];

    const int tid = threadIdx.x;
    const int wid = tid >> 5, lane = tid & 31;
    const int wm = (wid >> 1) * 32;       // warp M origin (0,32,64,96)
    const int wn = (wid & 1) * 32;        // warp N origin (0,32)
    const int g  = lane >> 2;             // groupID (0..7)
    const int tg = lane & 3;              // thread-in-group (0..3)
    const int r0 = blockIdx.x * 128;

    float acc[2][4][4];
    #pragma unroll
    for (int mi = 0; mi < 2; mi++)
        #pragma unroll
        for (int ni = 0; ni < 4; ni++)
            #pragma unroll
            for (int e = 0; e < 4; e++) acc[mi][ni][e] = 0.f;

    const float* wbase = W + (size_t)kk * ZD * CD;

    for (int ch = 0; ch < CD / KC; ch++) {
        const int k0g = ch * KC;

        // ---- load + split c tile: 128 rows x 32 d (4 float4 per thread) ----
        #pragma unroll
        for (int i = 0; i < 4; i++) {
            int idx = tid + i * 256;          // < 1024
            int row = idx >> 3, q = idx & 7;  // 8 float4 per row
            int r = r0 + row;
            int su = r / LEN, l = r - su * LEN;
            float4 v = *(const float4*)(c + ((size_t)su * T_DIM + l) * CD
                                          + k0g + q * 4);
            __nv_bfloat16 hx = __float2bfloat16(v.x);
            __nv_bfloat16 hy = __float2bfloat16(v.y);
            __nv_bfloat16 hz = __float2bfloat16(v.z);
            __nv_bfloat16 hw = __float2bfloat16(v.w);
            uint2 hi = make_uint2(bpack(hx, hy), bpack(hz, hw));
            uint2 lo = make_uint2(
                bpack(__float2bfloat16(v.x - __bfloat162float(hx)),
                      __float2bfloat16(v.y - __bfloat162float(hy))),
                bpack(__float2bfloat16(v.z - __bfloat162float(hz)),
                      __float2bfloat16(v.w - __bfloat162float(hw))));
            *(uint2*)&Ahi[row * SA + q * 4] = hi;
            *(uint2*)&Alo[row * SA + q * 4] = lo;
        }
        // ---- load + split W tile: 64 z x 32 d (2 float4 per thread) ----
        #pragma unroll
        for (int i = 0; i < 2; i++) {
            int idx = tid + i * 256;          // < 512
            int row = idx >> 3, q = idx & 7;
            float4 v = *(const float4*)(wbase + (size_t)row * CD + k0g + q * 4);
            __nv_bfloat16 hx = __float2bfloat16(v.x);
            __nv_bfloat16 hy = __float2bfloat16(v.y);
            __nv_bfloat16 hz = __float2bfloat16(v.z);
            __nv_bfloat16 hw = __float2bfloat16(v.w);
            uint2 hi = make_uint2(bpack(hx, hy), bpack(hz, hw));
            uint2 lo = make_uint2(
                bpack(__float2bfloat16(v.x - __bfloat162float(hx)),
                      __float2bfloat16(v.y - __bfloat162float(hy))),
                bpack(__float2bfloat16(v.z - __bfloat162float(hz)),
                      __float2bfloat16(v.w - __bfloat162float(hw))));
            *(uint2*)&Bhi[row * SB + q * 4] = hi;
            *(uint2*)&Blo[row * SB + q * 4] = lo;
        }
        __syncthreads();

        // ---- 2 k-steps of 16 ----
        #pragma unroll
        for (int ks = 0; ks < 2; ks++) {
            const int k0 = ks * 16;

            // A fragments (documented layout): a0=[g][tg*2], a1=[g+8][tg*2],
            // a2=[g][tg*2+8], a3=[g+8][tg*2+8] (rows m, cols k)
            uint32_t ahi[2][4], alo[2][4];
            #pragma unroll
            for (int mi = 0; mi < 2; mi++) {
                int rA = (wm + mi * 16 + g) * SA + k0 + tg * 2;
                ahi[mi][0] = *(const uint32_t*)&Ahi[rA];
                ahi[mi][1] = *(const uint32_t*)&Ahi[rA + 8 * SA];
                ahi[mi][2] = *(const uint32_t*)&Ahi[rA + 8];
                ahi[mi][3] = *(const uint32_t*)&Ahi[rA + 8 * SA + 8];
                alo[mi][0] = *(const uint32_t*)&Alo[rA];
                alo[mi][1] = *(const uint32_t*)&Alo[rA + 8 * SA];
                alo[mi][2] = *(const uint32_t*)&Alo[rA + 8];
                alo[mi][3] = *(const uint32_t*)&Alo[rA + 8 * SA + 8];
            }
            // B fragments: b0 = {B[k=tg*2][n=g], B[tg*2+1][g]} = W[n=g] k-pair
            uint32_t bhi[4][2], blo[4][2];
            #pragma unroll
            for (int ni = 0; ni < 4; ni++) {
                int rB = (wn + ni * 8 + g) * SB + k0 + tg * 2;
                bhi[ni][0] = *(const uint32_t*)&Bhi[rB];
                bhi[ni][1] = *(const uint32_t*)&Bhi[rB + 8];
                blo[ni][0] = *(const uint32_t*)&Blo[rB];
                blo[ni][1] = *(const uint32_t*)&Blo[rB + 8];
            }
            #pragma unroll
            for (int mi = 0; mi < 2; mi++)
                #pragma unroll
                for (int ni = 0; ni < 4; ni++) {
                    mma16816(acc[mi][ni], ahi[mi], bhi[ni]);
                    mma16816(acc[mi][ni], ahi[mi], blo[ni]);
                    mma16816(acc[mi][ni], alo[mi], bhi[ni]);
                    mma16816(acc[mi][ni], alo[mi], blo[ni]);
                }
        }
        __syncthreads();
    }

    // ---- epilogue: D layout c0=[g][tg*2], c1=[g][tg*2+1], c2/c3 row g+8 ----
    #pragma unroll
    for (int mi = 0; mi < 2; mi++) {
        #pragma unroll
        for (int ni = 0; ni < 4; ni++) {
            int col = wn + ni * 8 + tg * 2;
            float b0 = bias[kk * ZD + col];
            float b1 = bias[kk * ZD + col + 1];
            size_t rowA = (size_t)(r0 + wm + mi * 16 + g);
            *(float2*)(g_Wc + rowA * ZD + col) =
                make_float2(acc[mi][ni][0] + b0, acc[mi][ni][1] + b1);
            *(float2*)(g_Wc + (rowA + 8) * ZD + col) =
                make_float2(acc[mi][ni][2] + b0, acc[mi][ni][3] + b1);
        }
    }
}

// ---------------------------------------------------------------------------
// Kernel 2: scoring for step k (unchanged, measured ~38us/launch).
// ---------------------------------------------------------------------------
__global__ __launch_bounds__(256) void score_kernel(
    const float* __restrict__ z, const int* __restrict__ bidx,
    const int* __restrict__ sidx, const int kk)
{
    const int su = blockIdx.y;
    const int s = su >> 3, u = su & 7;
    const int tid = threadIdx.x;

    __shared__ int sbi[NEG];
    __shared__ float blk_loss;
    __shared__ int   blk_acc;
    if (tid < NEG) sbi[tid] = bidx[(kk * U_DIM + u) * NEG + tid];
    if (tid == 0) { blk_loss = 0.f; blk_acc = 0; }
    __syncthreads();

    const int warp = tid >> 5, lane = tid & 31;
    const int grp = lane >> 3, lg = lane & 7;
    const int gg = (blockIdx.x * 8 + warp) * 4 + grp;   // 0..383
    const int d0 = lg * 8;

    const float* wcb = g_Wc + (size_t)su * LEN * ZD;
    const int*   sib = sidx + ((((size_t)kk * S_DIM + s) * U_DIM + u) * NEG) * LEN;
    const float* zsp = z + (size_t)(s * U_DIM) * T_DIM * ZD;

    float loss_local = 0.f;
    int   acc_local  = 0;

    #pragma unroll
    for (int it = 0; it < 3; it++) {
        const int l = gg + 384 * it;
        const bool valid = (l < LEN);
        const int lx = valid ? l : 0;

        const float4 wa = *(const float4*)(wcb + (size_t)lx * ZD + d0);
        const float4 wb = *(const float4*)(wcb + (size_t)lx * ZD + d0 + 4);

        float f[NEG + 1];
        {
            const float* zr = z + ((size_t)su * T_DIM + (lx + kk + 1)) * ZD + d0;
            const float4 p0 = *(const float4*)zr;
            const float4 p1 = *(const float4*)(zr + 4);
            f[0] = p0.x * wa.x + p0.y * wa.y + p0.z * wa.z + p0.w * wa.w
                 + p1.x * wb.x + p1.y * wb.y + p1.z * wb.z + p1.w * wb.w;
        }
        #pragma unroll
        for (int n = 0; n < NEG; n++) {
            const int si = sib[(size_t)n * LEN + lx];
            const int bi = sbi[n];
            const float* zr = zsp + ((size_t)bi * T_DIM + (si + kk + 1)) * ZD + d0;
            const float4 p0 = *(const float4*)zr;
            const float4 p1 = *(const float4*)(zr + 4);
            f[1 + n] = p0.x * wa.x + p0.y * wa.y + p0.z * wa.z + p0.w * wa.w
                     + p1.x * wb.x + p1.y * wb.y + p1.z * wb.z + p1.w * wb.w;
        }

        #pragma unroll
        for (int off = 4; off; off >>= 1)
            #pragma unroll
            for (int i = 0; i < NEG + 1; i++)
                f[i] += __shfl_xor_sync(0xffffffffu, f[i], off);

        f[0] *= SCALE;
        float m = f[0]; int am = 0;
        #pragma unroll
        for (int i = 1; i < NEG + 1; i++) {
            f[i] *= SCALE;
            if (f[i] > m) { m = f[i]; am = i; }
        }
        float ssum = 0.f;
        #pragma unroll
        for (int i = 0; i < NEG + 1; i++) ssum += __expf(f[i] - m);

        if (valid) {
            loss_local += (m + __logf(ssum)) - f[0];
            acc_local  += (am == 0) ? 1 : 0;
        }
    }

    float lval = (lg == 0) ? loss_local : 0.f;
    int   aval = (lg == 0) ? acc_local  : 0;
    lval += __shfl_xor_sync(0xffffffffu, lval, 8);
    lval += __shfl_xor_sync(0xffffffffu, lval, 16);
    aval += __shfl_xor_sync(0xffffffffu, aval, 8);
    aval += __shfl_xor_sync(0xffffffffu, aval, 16);
    if (lane == 0) {
        atomicAdd(&blk_loss, lval);
        atomicAdd(&blk_acc, aval);
    }
    __syncthreads();
    if (tid == 0) {
        atomicAdd(&g_loss[kk], (double)blk_loss);
        atomicAdd(&g_acc[kk], blk_acc);
    }
}

// ---------------------------------------------------------------------------
// zero / finalize.  d_out layout: [loss, acc_0 .. acc_11]
// ---------------------------------------------------------------------------
__global__ void zero_kernel()
{
    int t = threadIdx.x;
    if (t < NK) { g_loss[t] = 0.0; g_acc[t] = 0; }
}

__global__ void final_kernel(float* __restrict__ out)
{
    int t = threadIdx.x;
    if (t < NK)
        out[1 + t] = (float)((double)g_acc[t] / (double)(SU * LEN));
    if (t == 0) {
        double tot = 0.0;
        for (int i = 0; i < NK; i++) tot += g_loss[i];   // fixed order
        out[0] = (float)(tot / ((double)NK * SU * LEN));
    }
}

// ---------------------------------------------------------------------------
extern "C" void kernel_launch(void* const* d_in, const int* in_sizes, int n_in,
                              void* d_out, int out_size)
{
    const float* z    = (const float*)d_in[0];
    const float* c    = (const float*)d_in[1];
    const float* W    = (const float*)d_in[2];
    const float* b    = (const float*)d_in[3];
    const int*   bidx = (const int*)d_in[4];
    const int*   sidx = (const int*)d_in[5];
    float* out = (float*)d_out;

    zero_kernel<<<1, 32>>>();
    for (int kk = 0; kk < NK; kk++) {
        gemm_hmma<<<564, 256>>>(c, W, b, kk);
        score_kernel<<<dim3(12, SU), 256>>>(z, bidx, sidx, kk);
    }
    final_kernel<<<1, 32>>>(out);
}

// round 9
// speedup vs baseline: 1.7775x; 1.3909x over previous
#include <cuda_runtime.h>
#include <cuda_bf16.h>
#include <cstdint>
#include <cstddef>

#define S_DIM 8
#define U_DIM 8
#define SU    64
#define NK    12
#define NEG   17
#define ZD    64
#define CD    256
#define T_DIM 1140
#define LEN   1128
#define MROWS (SU * LEN)          // 72192 flattened (su,l) rows = 564 * 128
#define SCALE 0.125f

// Scratch: Wc[k][su*LEN + l][z]  (~222 MB)
__device__ float  g_Wc[(size_t)NK * MROWS * ZD];
__device__ double g_loss[NK];
__device__ int    g_acc[NK];

// ---------------------------------------------------------------------------
// bf16 helpers
// ---------------------------------------------------------------------------
__device__ __forceinline__ uint32_t bpack(__nv_bfloat16 x, __nv_bfloat16 y)
{
    __nv_bfloat162 t = __halves2bfloat162(x, y);
    return *reinterpret_cast<uint32_t*>(&t);
}

// mma.sync m16n8k16 bf16: d += a * b   (f32 accumulate)
__device__ __forceinline__ void mma16816(float* d, const uint32_t* a,
                                         const uint32_t* b)
{
    asm volatile(
        "mma.sync.aligned.m16n8k16.row.col.f32.bf16.bf16.f32 "
        "{%0,%1,%2,%3}, {%4,%5,%6,%7}, {%8,%9}, {%0,%1,%2,%3};"
        : "+f"(d[0]), "+f"(d[1]), "+f"(d[2]), "+f"(d[3])
        : "r"(a[0]), "r"(a[1]), "r"(a[2]), "r"(a[3]), "r"(b[0]), "r"(b[1]));
}

// ---------------------------------------------------------------------------
// Kernel 1: ONE launch for all k.
// Wc[k][r][z] = sum_d c_row(r)[d] * W[k][z][d] + b[k][z]
// 2-term bf16 split with lo*lo dropped (3 cross-products; residual ~2^-18).
// Grid (12, 564): x = k (fastest -> 12 CTAs sharing a c row-tile are
// launch-adjacent, c row-tile hits L2 11 of 12 times), y = row tile.
// CTA = 128 rows x 64 z x K=256 (8 chunks of 32). Warp tile 32x32.
// Smem stride 40 bf16: (20g + tg) mod 32 is a permutation -> conflict-free.
// ---------------------------------------------------------------------------
#define KC 32
#define SA 40
#define SB 40

__global__ __launch_bounds__(256) void gemm_hmma(
    const float* __restrict__ c, const float* __restrict__ W,
    const float* __restrict__ bias)
{
    __shared__ __align__(16) __nv_bfloat16 Ahi[128 * SA];
    __shared__ __align__(16) __nv_bfloat16 Alo[128 * SA];
    __shared__ __align__(16) __nv_bfloat16 Bhi[ZD * SB];
    __shared__ __align__(16) __nv_bfloat16 Blo[ZD * SB];

    const int kk  = blockIdx.x;
    const int tid = threadIdx.x;
    const int wid = tid >> 5, lane = tid & 31;
    const int wm = (wid >> 1) * 32;       // warp M origin (0,32,64,96)
    const int wn = (wid & 1) * 32;        // warp N origin (0,32)
    const int g  = lane >> 2;             // groupID (0..7)
    const int tg = lane & 3;              // thread-in-group (0..3)
    const int r0 = blockIdx.y * 128;

    float acc[2][4][4];
    #pragma unroll
    for (int mi = 0; mi < 2; mi++)
        #pragma unroll
        for (int ni = 0; ni < 4; ni++)
            #pragma unroll
            for (int e = 0; e < 4; e++) acc[mi][ni][e] = 0.f;

    const float* wbase = W + (size_t)kk * ZD * CD;

    for (int ch = 0; ch < CD / KC; ch++) {
        const int k0g = ch * KC;

        // ---- load + split c tile: 128 rows x 32 d (4 float4 per thread) ----
        #pragma unroll
        for (int i = 0; i < 4; i++) {
            int idx = tid + i * 256;          // < 1024
            int row = idx >> 3, q = idx & 7;  // 8 float4 per row
            int r = r0 + row;
            int su = r / LEN, l = r - su * LEN;
            float4 v = *(const float4*)(c + ((size_t)su * T_DIM + l) * CD
                                          + k0g + q * 4);
            __nv_bfloat16 hx = __float2bfloat16(v.x);
            __nv_bfloat16 hy = __float2bfloat16(v.y);
            __nv_bfloat16 hz = __float2bfloat16(v.z);
            __nv_bfloat16 hw = __float2bfloat16(v.w);
            uint2 hi = make_uint2(bpack(hx, hy), bpack(hz, hw));
            uint2 lo = make_uint2(
                bpack(__float2bfloat16(v.x - __bfloat162float(hx)),
                      __float2bfloat16(v.y - __bfloat162float(hy))),
                bpack(__float2bfloat16(v.z - __bfloat162float(hz)),
                      __float2bfloat16(v.w - __bfloat162float(hw))));
            *(uint2*)&Ahi[row * SA + q * 4] = hi;
            *(uint2*)&Alo[row * SA + q * 4] = lo;
        }
        // ---- load + split W tile: 64 z x 32 d (2 float4 per thread) ----
        #pragma unroll
        for (int i = 0; i < 2; i++) {
            int idx = tid + i * 256;          // < 512
            int row = idx >> 3, q = idx & 7;
            float4 v = *(const float4*)(wbase + (size_t)row * CD + k0g + q * 4);
            __nv_bfloat16 hx = __float2bfloat16(v.x);
            __nv_bfloat16 hy = __float2bfloat16(v.y);
            __nv_bfloat16 hz = __float2bfloat16(v.z);
            __nv_bfloat16 hw = __float2bfloat16(v.w);
            uint2 hi = make_uint2(bpack(hx, hy), bpack(hz, hw));
            uint2 lo = make_uint2(
                bpack(__float2bfloat16(v.x - __bfloat162float(hx)),
                      __float2bfloat16(v.y - __bfloat162float(hy))),
                bpack(__float2bfloat16(v.z - __bfloat162float(hz)),
                      __float2bfloat16(v.w - __bfloat162float(hw))));
            *(uint2*)&Bhi[row * SB + q * 4] = hi;
            *(uint2*)&Blo[row * SB + q * 4] = lo;
        }
        __syncthreads();

        // ---- 2 k-steps of 16 ----
        #pragma unroll
        for (int ks = 0; ks < 2; ks++) {
            const int k0 = ks * 16;

            uint32_t ahi[2][4], alo[2][4];
            #pragma unroll
            for (int mi = 0; mi < 2; mi++) {
                int rA = (wm + mi * 16 + g) * SA + k0 + tg * 2;
                ahi[mi][0] = *(const uint32_t*)&Ahi[rA];
                ahi[mi][1] = *(const uint32_t*)&Ahi[rA + 8 * SA];
                ahi[mi][2] = *(const uint32_t*)&Ahi[rA + 8];
                ahi[mi][3] = *(const uint32_t*)&Ahi[rA + 8 * SA + 8];
                alo[mi][0] = *(const uint32_t*)&Alo[rA];
                alo[mi][1] = *(const uint32_t*)&Alo[rA + 8 * SA];
                alo[mi][2] = *(const uint32_t*)&Alo[rA + 8];
                alo[mi][3] = *(const uint32_t*)&Alo[rA + 8 * SA + 8];
            }
            uint32_t bhi[4][2], blo[4][2];
            #pragma unroll
            for (int ni = 0; ni < 4; ni++) {
                int rB = (wn + ni * 8 + g) * SB + k0 + tg * 2;
                bhi[ni][0] = *(const uint32_t*)&Bhi[rB];
                bhi[ni][1] = *(const uint32_t*)&Bhi[rB + 8];
                blo[ni][0] = *(const uint32_t*)&Blo[rB];
                blo[ni][1] = *(const uint32_t*)&Blo[rB + 8];
            }
            #pragma unroll
            for (int mi = 0; mi < 2; mi++)
                #pragma unroll
                for (int ni = 0; ni < 4; ni++) {
                    mma16816(acc[mi][ni], ahi[mi], bhi[ni]);
                    mma16816(acc[mi][ni], ahi[mi], blo[ni]);
                    mma16816(acc[mi][ni], alo[mi], bhi[ni]);
                    // lo x lo dropped: contributes ~2^-18 relative
                }
        }
        __syncthreads();
    }

    // ---- epilogue ----
    float* wcout = g_Wc + (size_t)kk * MROWS * ZD;
    #pragma unroll
    for (int mi = 0; mi < 2; mi++) {
        #pragma unroll
        for (int ni = 0; ni < 4; ni++) {
            int col = wn + ni * 8 + tg * 2;
            float b0 = bias[kk * ZD + col];
            float b1 = bias[kk * ZD + col + 1];
            size_t rowA = (size_t)(r0 + wm + mi * 16 + g);
            *(float2*)(wcout + rowA * ZD + col) =
                make_float2(acc[mi][ni][0] + b0, acc[mi][ni][1] + b1);
            *(float2*)(wcout + (rowA + 8) * ZD + col) =
                make_float2(acc[mi][ni][2] + b0, acc[mi][ni][3] + b1);
        }
    }
}

// ---------------------------------------------------------------------------
// Kernel 2: ONE scoring launch for all k.  Grid (12, 64, 12): z-dim = k.
// 8-lane groups own one l; lane owns 8 of 64 dims. Warp = 4 l's.
// ---------------------------------------------------------------------------
__global__ __launch_bounds__(256) void score_kernel(
    const float* __restrict__ z, const int* __restrict__ bidx,
    const int* __restrict__ sidx)
{
    const int kk = blockIdx.z;
    const int su = blockIdx.y;
    const int s = su >> 3, u = su & 7;
    const int tid = threadIdx.x;

    __shared__ int sbi[NEG];
    __shared__ float blk_loss;
    __shared__ int   blk_acc;
    if (tid < NEG) sbi[tid] = bidx[(kk * U_DIM + u) * NEG + tid];
    if (tid == 0) { blk_loss = 0.f; blk_acc = 0; }
    __syncthreads();

    const int warp = tid >> 5, lane = tid & 31;
    const int grp = lane >> 3, lg = lane & 7;
    const int gg = (blockIdx.x * 8 + warp) * 4 + grp;   // 0..383
    const int d0 = lg * 8;

    const float* wcb = g_Wc + ((size_t)kk * MROWS + (size_t)su * LEN) * ZD;
    const int*   sib = sidx + ((((size_t)kk * S_DIM + s) * U_DIM + u) * NEG) * LEN;
    const float* zsp = z + (size_t)(s * U_DIM) * T_DIM * ZD;

    float loss_local = 0.f;
    int   acc_local  = 0;

    #pragma unroll
    for (int it = 0; it < 3; it++) {
        const int l = gg + 384 * it;
        const bool valid = (l < LEN);
        const int lx = valid ? l : 0;

        const float4 wa = *(const float4*)(wcb + (size_t)lx * ZD + d0);
        const float4 wb = *(const float4*)(wcb + (size_t)lx * ZD + d0 + 4);

        float f[NEG + 1];
        {
            const float* zr = z + ((size_t)su * T_DIM + (lx + kk + 1)) * ZD + d0;
            const float4 p0 = *(const float4*)zr;
            const float4 p1 = *(const float4*)(zr + 4);
            f[0] = p0.x * wa.x + p0.y * wa.y + p0.z * wa.z + p0.w * wa.w
                 + p1.x * wb.x + p1.y * wb.y + p1.z * wb.z + p1.w * wb.w;
        }
        #pragma unroll
        for (int n = 0; n < NEG; n++) {
            const int si = sib[(size_t)n * LEN + lx];
            const int bi = sbi[n];
            const float* zr = zsp + ((size_t)bi * T_DIM + (si + kk + 1)) * ZD + d0;
            const float4 p0 = *(const float4*)zr;
            const float4 p1 = *(const float4*)(zr + 4);
            f[1 + n] = p0.x * wa.x + p0.y * wa.y + p0.z * wa.z + p0.w * wa.w
                     + p1.x * wb.x + p1.y * wb.y + p1.z * wb.z + p1.w * wb.w;
        }

        #pragma unroll
        for (int off = 4; off; off >>= 1)
            #pragma unroll
            for (int i = 0; i < NEG + 1; i++)
                f[i] += __shfl_xor_sync(0xffffffffu, f[i], off);

        f[0] *= SCALE;
        float m = f[0]; int am = 0;
        #pragma unroll
        for (int i = 1; i < NEG + 1; i++) {
            f[i] *= SCALE;
            if (f[i] > m) { m = f[i]; am = i; }
        }
        float ssum = 0.f;
        #pragma unroll
        for (int i = 0; i < NEG + 1; i++) ssum += __expf(f[i] - m);

        if (valid) {
            loss_local += (m + __logf(ssum)) - f[0];
            acc_local  += (am == 0) ? 1 : 0;
        }
    }

    float lval = (lg == 0) ? loss_local : 0.f;
    int   aval = (lg == 0) ? acc_local  : 0;
    lval += __shfl_xor_sync(0xffffffffu, lval, 8);
    lval += __shfl_xor_sync(0xffffffffu, lval, 16);
    aval += __shfl_xor_sync(0xffffffffu, aval, 8);
    aval += __shfl_xor_sync(0xffffffffu, aval, 16);
    if (lane == 0) {
        atomicAdd(&blk_loss, lval);
        atomicAdd(&blk_acc, aval);
    }
    __syncthreads();
    if (tid == 0) {
        atomicAdd(&g_loss[kk], (double)blk_loss);
        atomicAdd(&g_acc[kk], blk_acc);
    }
}

// ---------------------------------------------------------------------------
// zero / finalize.  d_out layout: [loss, acc_0 .. acc_11]
// ---------------------------------------------------------------------------
__global__ void zero_kernel()
{
    int t = threadIdx.x;
    if (t < NK) { g_loss[t] = 0.0; g_acc[t] = 0; }
}

__global__ void final_kernel(float* __restrict__ out)
{
    int t = threadIdx.x;
    if (t < NK)
        out[1 + t] = (float)((double)g_acc[t] / (double)(SU * LEN));
    if (t == 0) {
        double tot = 0.0;
        for (int i = 0; i < NK; i++) tot += g_loss[i];   // fixed order
        out[0] = (float)(tot / ((double)NK * SU * LEN));
    }
}

// ---------------------------------------------------------------------------
extern "C" void kernel_launch(void* const* d_in, const int* in_sizes, int n_in,
                              void* d_out, int out_size)
{
    const float* z    = (const float*)d_in[0];
    const float* c    = (const float*)d_in[1];
    const float* W    = (const float*)d_in[2];
    const float* b    = (const float*)d_in[3];
    const int*   bidx = (const int*)d_in[4];
    const int*   sidx = (const int*)d_in[5];
    float* out = (float*)d_out;

    zero_kernel<<<1, 32>>>();
    gemm_hmma<<<dim3(NK, 564), 256>>>(c, W, b);
    score_kernel<<<dim3(12, SU, NK), 256>>>(z, bidx, sidx);
    final_kernel<<<1, 32>>>(out);
}